// round 14
// baseline (speedup 1.0000x reference)
#include <cuda_runtime.h>
#include <math.h>

#define NN 100000
#define NE 1600000
#define ET (NE + NN)        // edges incl. self loops
#define HD 64
#define NC 16
#define NBLK ((NN + 255) / 256)   // 391

// ---------------- scratch (device globals; no allocation allowed) ----------
__device__ __align__(16) int   g_srcs[ET];       // CSR: src per edge, grouped by dst
__device__ int   g_rowstart[NN + 1];
__device__ int   g_deg[NN];                      // zero at load; re-zeroed by scan1
__device__ int   g_cursor[NN];
__device__ int   g_bsums[512];
__device__ __align__(16) float g_h[NN * HD];     // transformed features (fp32)
__device__ __align__(16) float g_x1[NN * HD];    // layer-1 output (after elu)
__device__ __align__(16) float g_x2[NN * HD];    // fallback layer-2 output
__device__ float g_as[NN];
__device__ float g_ad[NN];

__device__ __forceinline__ int clampN(int v) {
    return (v < 0) ? 0 : (v >= NN ? NN - 1 : v);
}

// ---------------- CSR build ------------------------------------------------
__global__ void k_hist(const int* __restrict__ adj) {
    int i = blockIdx.x * blockDim.x + threadIdx.x;
    int stride = gridDim.x * blockDim.x;
    for (int e = i; e < NE; e += stride)
        atomicAdd(&g_deg[clampN(adj[NE + e])], 1);
}

__global__ void k_scan1() {
    __shared__ int sh[256];
    int t = threadIdx.x;
    int idx = blockIdx.x * 256 + t;
    int v = 0;
    if (idx < NN) {
        v = g_deg[idx] + 1;      // +1: self loop
        g_deg[idx] = 0;          // reset for next graph replay
    }
    int x = v;
    sh[t] = x;
    __syncthreads();
    #pragma unroll
    for (int off = 1; off < 256; off <<= 1) {
        int y = (t >= off) ? sh[t - off] : 0;
        __syncthreads();
        x += y;
        sh[t] = x;
        __syncthreads();
    }
    if (idx < NN) g_rowstart[idx] = x - v;   // exclusive, partial
    if (t == 255) g_bsums[blockIdx.x] = x;   // block total
}

// scan2+scan3 merged; also pre-places the self loop at slot rowstart[n].
__global__ void k_scan23() {
    __shared__ int sh[256];
    int b = blockIdx.x, t = threadIdx.x;

    int s = 0;
    if (t < b) s += g_bsums[t];
    int t2 = t + 256;
    if (t2 < b) s += g_bsums[t2];
    sh[t] = s;
    __syncthreads();
    #pragma unroll
    for (int off = 128; off; off >>= 1) {
        if (t < off) sh[t] += sh[t + off];
        __syncthreads();
    }
    int base = sh[0];

    int idx = b * 256 + t;
    if (idx < NN) {
        int r = g_rowstart[idx] + base;
        g_rowstart[idx] = r;
        g_srcs[r] = idx;          // self loop occupies first slot
        g_cursor[idx] = r + 1;    // scatter fills the rest
    }
    if (b == NBLK - 1 && t == 0)
        g_rowstart[NN] = base + g_bsums[NBLK - 1];   // total == ET
}

__global__ void k_scatter(const int* __restrict__ adj) {
    int i = blockIdx.x * blockDim.x + threadIdx.x;
    int stride = gridDim.x * blockDim.x;
    for (int e = i; e < NE; e += stride) {
        int s = clampN(adj[e]);
        int d = clampN(adj[NE + e]);
        int pos = atomicAdd(&g_cursor[d], 1);
        g_srcs[pos] = s;
    }
}

// ---------------- fused GEMM (h = X@W) + alpha dots ------------------------
// 128 nodes x 64 cols per block, 128 threads, 8x8 register tile.
// Rows r = ty + 16i, cols c = tx + 8j (interleaved; stride-36 smem ->
// conflict-free scalar LDS). bytes/FMA = 1 -> balanced vs FMA pipe.
template <int K, bool FROM_G>
__global__ void __launch_bounds__(128) k_gemm(
    const float* __restrict__ Xext, const float* __restrict__ W,
    const float* __restrict__ asrc, const float* __restrict__ adst)
{
    __shared__ float Xs[128 * 36];   // [row][k], K-tile 32, stride 36
    __shared__ float Ws[64 * 36];    // [col][k] transposed, stride 36

    const float* X = FROM_G ? g_x1 : Xext;

    int tid = threadIdx.x;
    int ty = tid >> 3;      // 0..15
    int tx = tid & 7;       // 0..7
    int nbase = blockIdx.x * 128;

    float acc[8][8];
    #pragma unroll
    for (int i = 0; i < 8; i++)
        #pragma unroll
        for (int j = 0; j < 8; j++) acc[i][j] = 0.f;

    for (int kt = 0; kt < K; kt += 32) {
        // load X tile (128 rows x 32 k), coalesced float4
        #pragma unroll
        for (int t = 0; t < 8; t++) {
            int f = tid + t * 128;         // 0..1023
            int r = f >> 3;
            int c4 = f & 7;
            int rg = nbase + r;
            if (rg >= NN) rg = NN - 1;
            float4 v = *(const float4*)(X + (size_t)rg * K + kt + c4 * 4);
            *(float4*)(Xs + r * 36 + c4 * 4) = v;
        }
        // load W tile transposed (32 k x 64 cols), coalesced global
        #pragma unroll
        for (int t = 0; t < 16; t++) {
            int f = tid + t * 128;         // 0..2047
            int kk = f >> 6;
            int c  = f & 63;
            Ws[c * 36 + kk] = W[(kt + kk) * 64 + c];
        }
        __syncthreads();

        #pragma unroll
        for (int kk = 0; kk < 32; kk++) {
            float xv[8], wv[8];
            #pragma unroll
            for (int i = 0; i < 8; i++) xv[i] = Xs[(ty + 16 * i) * 36 + kk];
            #pragma unroll
            for (int j = 0; j < 8; j++) wv[j] = Ws[(tx + 8 * j) * 36 + kk];
            #pragma unroll
            for (int i = 0; i < 8; i++)
                #pragma unroll
                for (int j = 0; j < 8; j++)
                    acc[i][j] += xv[i] * wv[j];
        }
        __syncthreads();
    }

    // epilogue: h store + alpha dots (reduce over the 8 tx lanes)
    float asc[8], adc[8];
    #pragma unroll
    for (int j = 0; j < 8; j++) {
        int col = tx + 8 * j;
        asc[j] = asrc[col];
        adc[j] = adst[col];
    }
    #pragma unroll
    for (int i = 0; i < 8; i++) {
        int node = nbase + ty + 16 * i;
        float ps = 0.f, pd = 0.f;
        #pragma unroll
        for (int j = 0; j < 8; j++) {
            ps += acc[i][j] * asc[j];
            pd += acc[i][j] * adc[j];
        }
        #pragma unroll
        for (int off = 4; off; off >>= 1) {
            ps += __shfl_xor_sync(0xffffffffu, ps, off);
            pd += __shfl_xor_sync(0xffffffffu, pd, off);
        }
        if (node < NN) {
            #pragma unroll
            for (int j = 0; j < 8; j++)
                g_h[(size_t)node * 64 + tx + 8 * j] = acc[i][j];
            if (tx == 0) { g_as[node] = ps; g_ad[node] = pd; }
        }
    }
}

// ---------------- GAT aggregation: one warp per destination node -----------
// Unshifted softmax (ratio identical to max-shifted; logits Xavier-scaled,
// |e| << 88 so no overflow). Lane covers dims {2*lane, 2*lane+1} via LDG.64.
// 4-edge unroll: batch index loads -> alpha gathers -> feature gathers.
// MODE 0: write external out (no elu); MODE 1: g_x1 (elu); MODE 2: g_x2.
template <int MODE>
__global__ void __launch_bounds__(256) k_agg(
    const float* __restrict__ bias, float* __restrict__ outext)
{
    int warp = (blockIdx.x * blockDim.x + threadIdx.x) >> 5;
    int lane = threadIdx.x & 31;
    if (warp >= NN) return;

    float* out = (MODE == 1) ? g_x1 : (MODE == 2 ? g_x2 : outext);

    int beg = g_rowstart[warp];
    int end = g_rowstart[warp + 1];
    float adr = g_ad[warp];

    float ssum = 0.f, a0 = 0.f, a1 = 0.f;
    int e = beg;
    for (; e + 4 <= end; e += 4) {
        int s0 = g_srcs[e];
        int s1 = g_srcs[e + 1];
        int s2 = g_srcs[e + 2];
        int s3 = g_srcs[e + 3];
        float v0 = g_as[s0];
        float v1 = g_as[s1];
        float v2 = g_as[s2];
        float v3 = g_as[s3];
        float2 h0 = ((const float2*)(g_h + (size_t)s0 * 64))[lane];
        float2 h1 = ((const float2*)(g_h + (size_t)s1 * 64))[lane];
        float2 h2 = ((const float2*)(g_h + (size_t)s2 * 64))[lane];
        float2 h3 = ((const float2*)(g_h + (size_t)s3 * 64))[lane];
        v0 += adr; v1 += adr; v2 += adr; v3 += adr;
        v0 = (v0 > 0.f) ? v0 : 0.2f * v0;
        v1 = (v1 > 0.f) ? v1 : 0.2f * v1;
        v2 = (v2 > 0.f) ? v2 : 0.2f * v2;
        v3 = (v3 > 0.f) ? v3 : 0.2f * v3;
        float p0 = __expf(v0);
        float p1 = __expf(v1);
        float p2 = __expf(v2);
        float p3 = __expf(v3);
        ssum += (p0 + p1) + (p2 + p3);
        a0 += p0 * h0.x + p1 * h1.x + p2 * h2.x + p3 * h3.x;
        a1 += p0 * h0.y + p1 * h1.y + p2 * h2.y + p3 * h3.y;
    }
    for (; e < end; e++) {
        int s = g_srcs[e];
        float v = g_as[s] + adr;
        v = (v > 0.f) ? v : 0.2f * v;
        float p = __expf(v);
        float2 h = ((const float2*)(g_h + (size_t)s * 64))[lane];
        ssum += p;
        a0 += p * h.x;
        a1 += p * h.y;
    }

    float2 bv = ((const float2*)bias)[lane];
    float inv = 1.0f / ssum;
    float o0 = a0 * inv + bv.x;
    float o1 = a1 * inv + bv.y;
    if (MODE == 1) {
        o0 = (o0 > 0.f) ? o0 : expm1f(o0);
        o1 = (o1 > 0.f) ? o1 : expm1f(o1);
    }
    ((float2*)(out + (size_t)warp * 64))[lane] = make_float2(o0, o1);
}

// ---------------- classifier ------------------------------------------------
template <bool FROM_G>
__global__ void __launch_bounds__(256) k_clf(
    const float* __restrict__ xext, const float* __restrict__ Wc,
    const float* __restrict__ bc, float* __restrict__ out)
{
    __shared__ float Ws[64 * 16];
    int tid = threadIdx.x;
    for (int i = tid; i < 64 * 16; i += 256) Ws[i] = Wc[i];
    __syncthreads();

    const float* x = FROM_G ? g_x2 : xext;

    int node = blockIdx.x * 16 + (tid >> 4);
    int col = tid & 15;
    if (node >= NN) return;
    float acc = bc[col];
    const float* xr = x + (size_t)node * 64;
    #pragma unroll
    for (int k = 0; k < 64; k += 4) {
        float4 xv = *(const float4*)(xr + k);
        acc += xv.x * Ws[(k + 0) * 16 + col];
        acc += xv.y * Ws[(k + 1) * 16 + col];
        acc += xv.z * Ws[(k + 2) * 16 + col];
        acc += xv.w * Ws[(k + 3) * 16 + col];
    }
    out[(size_t)node * 16 + col] = acc;
}

// ---------------- launch -----------------------------------------------------
extern "C" void kernel_launch(void* const* d_in, const int* in_sizes, int n_in,
                              void* d_out, int out_size) {
    const float* ft  = (const float*)d_in[0];
    const int*   adj = (const int*)d_in[1];     // int32 (JAX x64 disabled)
    const float* W1  = (const float*)d_in[2];
    const float* as1 = (const float*)d_in[3];
    const float* ad1 = (const float*)d_in[4];
    const float* b1  = (const float*)d_in[5];
    const float* W2  = (const float*)d_in[6];
    const float* as2 = (const float*)d_in[7];
    const float* ad2 = (const float*)d_in[8];
    const float* b2  = (const float*)d_in[9];
    const float* Wc  = (const float*)d_in[10];
    const float* bc  = (const float*)d_in[11];
    float* out = (float*)d_out;

    bool big_out = (out_size >= NN * (NC + HD));
    float* xout = out + (size_t)NN * NC;   // only used when big_out

    static cudaStream_t s_side = nullptr;
    static cudaEvent_t  ev_fork = nullptr, ev_join = nullptr;
    if (s_side == nullptr) {
        cudaStreamCreateWithFlags(&s_side, cudaStreamNonBlocking);
        cudaEventCreateWithFlags(&ev_fork, cudaEventDisableTiming);
        cudaEventCreateWithFlags(&ev_join, cudaEventDisableTiming);
    }

    int gemm_blocks = (NN + 127) / 128;      // 782
    int agg_blocks  = (NN * 32 + 255) / 256; // 12500
    int hist_blocks = (NE + 255) / 256;      // 6250
    int scat_blocks = (NE + 255) / 256;      // 6250

    // fork: CSR build on side stream, concurrent with layer-1 GEMM
    cudaEventRecord(ev_fork, 0);
    cudaStreamWaitEvent(s_side, ev_fork, 0);

    k_hist<<<hist_blocks, 256, 0, s_side>>>(adj);
    k_scan1<<<NBLK, 256, 0, s_side>>>();
    k_scan23<<<NBLK, 256, 0, s_side>>>();
    k_scatter<<<scat_blocks, 256, 0, s_side>>>(adj);
    cudaEventRecord(ev_join, s_side);

    // main stream: layer-1 GEMM overlaps CSR build
    k_gemm<128, false><<<gemm_blocks, 128>>>(ft, W1, as1, ad1);

    cudaStreamWaitEvent(0, ev_join, 0);
    k_agg<1><<<agg_blocks, 256>>>(b1, nullptr);

    // layer 2
    k_gemm<64, true><<<gemm_blocks, 128>>>(nullptr, W2, as2, ad2);
    if (big_out) {
        k_agg<0><<<agg_blocks, 256>>>(b2, xout);
        k_clf<false><<<(NN + 15) / 16, 256>>>(xout, Wc, bc, out);
    } else {
        k_agg<2><<<agg_blocks, 256>>>(b2, nullptr);
        k_clf<true><<<(NN + 15) / 16, 256>>>(nullptr, Wc, bc, out);
    }
}